// round 11
// baseline (speedup 1.0000x reference)
#include <cuda_runtime.h>
#include <cuda_fp16.h>
#include <mma.h>

using namespace nvcuda;

#define N_NODES 40000
#define N_EDGES 640000
#define D 128
#define CAP 96   // max in-degree bucket capacity (Binomial(640K,1/40K): mean 16, P(>96)~0)

// ---- device scratch (allocation-free rule: __device__ globals) ----
__device__ int    g_cnt[N_NODES];                // per-node fill counters (zeroed by gather)
__device__ float2 g_edge[(size_t)N_NODES * CAP]; // bucketed {src_bits, weight}
__device__ __half g_y[N_NODES * D];              // y = x @ W, fp16 (fp32 accumulated)
__device__ __half g_wh[D * D];                   // W converted to fp16

// ---------------------------------------------------------------
// single-pass bucketed CSR fill: 4 edges per thread, vectorized input reads
__global__ void k_fill(const int4* __restrict__ src4, const int4* __restrict__ dst4,
                       const float4* __restrict__ ew4) {
    int i = blockIdx.x * blockDim.x + threadIdx.x;
    if (i >= N_EDGES / 4) return;
    int4 s = src4[i];
    int4 d = dst4[i];
    float4 w = ew4[i];
    int p;
    p = atomicAdd(&g_cnt[d.x], 1);
    if (p < CAP) g_edge[(size_t)d.x * CAP + p] = make_float2(__int_as_float(s.x), w.x);
    p = atomicAdd(&g_cnt[d.y], 1);
    if (p < CAP) g_edge[(size_t)d.y * CAP + p] = make_float2(__int_as_float(s.y), w.y);
    p = atomicAdd(&g_cnt[d.z], 1);
    if (p < CAP) g_edge[(size_t)d.z * CAP + p] = make_float2(__int_as_float(s.z), w.z);
    p = atomicAdd(&g_cnt[d.w], 1);
    if (p < CAP) g_edge[(size_t)d.w * CAP + p] = make_float2(__int_as_float(s.w), w.w);
}

// W (128x128 f32) -> g_wh fp16, one-shot tiny kernel (runs before gemm on side stream)
__global__ void k_wh(const float* __restrict__ W) {
    int i = blockIdx.x * blockDim.x + threadIdx.x;   // 4096 threads, 4 floats each
    float4 wv = ((const float4*)W)[i];
    __half2 h0 = __floats2half2_rn(wv.x, wv.y);
    __half2 h1 = __floats2half2_rn(wv.z, wv.w);
    uint2 o;
    o.x = *(unsigned*)&h0;
    o.y = *(unsigned*)&h1;
    ((uint2*)g_wh)[i] = o;
}

// y = x @ W via tensor cores (wmma fp16 in / fp32 accum), fp16 store direct to global.
// Block tile: 128 rows x 128 cols, K=128. 8 warps, each warp: 16 rows x 128 cols.
// smem = xh (34.8KB) + wh (17.4KB) = 52.2KB -> 4 blocks/SM.
#define XH_LD 136   // half stride (pad 8)
__global__ void __launch_bounds__(256)
k_gemm(const float* __restrict__ x) {
    extern __shared__ char smem_raw[];
    __half* xh = (__half*)smem_raw;                       // 128 x XH_LD halves (34816 B)
    __half* wh = (__half*)(smem_raw + 128 * XH_LD * 2);   // 128 x XH_LD halves (17408 B used as 128 rows? no: fp16 W rows)

    int tid = threadIdx.x;
    int warp = tid >> 5;
    int r0 = blockIdx.x * 128;

    // load x tile (128x128 f32, row-guarded) -> xh fp16 (DRAM traffic, issue first)
    #pragma unroll
    for (int i = tid; i < 128 * 32; i += 256) {
        int row = i >> 5, c4 = i & 31;
        int gr = r0 + row;
        float4 xv = (gr < N_NODES) ? ((const float4*)x)[(size_t)gr * 32 + c4]
                                   : make_float4(0.f, 0.f, 0.f, 0.f);
        __half2 h0 = __floats2half2_rn(xv.x, xv.y);
        __half2 h1 = __floats2half2_rn(xv.z, xv.w);
        *(__half2*)&xh[row * XH_LD + c4 * 4]     = h0;
        *(__half2*)&xh[row * XH_LD + c4 * 4 + 2] = h1;
    }
    // load pre-converted W fp16 (L2-resident, 32KB) -> wh
    #pragma unroll
    for (int i = tid; i < 128 * 16; i += 256) {   // 16 uint4 (32 halves... 128 halves/row = 16 uint2? use uint2: 128*D halves = 2048 uint4)
        int row = i >> 4, c8 = i & 15;            // 16 chunks of 8 halves per row
        uint4 wv = ((const uint4*)g_wh)[(size_t)row * 16 + c8];
        *(uint4*)&wh[row * XH_LD + c8 * 8] = wv;
    }
    __syncthreads();

    wmma::fragment<wmma::accumulator, 16, 16, 16, float> acc[8];
    #pragma unroll
    for (int n = 0; n < 8; n++) wmma::fill_fragment(acc[n], 0.0f);

    #pragma unroll
    for (int k = 0; k < 128; k += 16) {
        wmma::fragment<wmma::matrix_a, 16, 16, 16, __half, wmma::row_major> a;
        wmma::load_matrix_sync(a, &xh[(warp * 16) * XH_LD + k], XH_LD);
        #pragma unroll
        for (int n = 0; n < 8; n++) {
            wmma::fragment<wmma::matrix_b, 16, 16, 16, __half, wmma::row_major> bf;
            wmma::load_matrix_sync(bf, &wh[k * XH_LD + n * 16], XH_LD);
            wmma::mma_sync(acc[n], a, bf, acc[n]);
        }
    }

    // epilogue: convert fp32 fragments -> fp16 fragments, store direct to global.
    // (last block is full: 40000 = 312*128 + 64, guard via row check is impossible
    //  per-fragment; instead rows beyond N_NODES are written to a scratch row range —
    //  g_y is sized for 40064 rows below to keep stores in-bounds.)
    #pragma unroll
    for (int n = 0; n < 8; n++) {
        wmma::fragment<wmma::accumulator, 16, 16, 16, __half> hacc;
        #pragma unroll
        for (int e = 0; e < hacc.num_elements; e++)
            hacc.x[e] = __float2half(acc[n].x[e]);
        wmma::store_matrix_sync(g_y + (size_t)(r0 + warp * 16) * D + n * 16,
                                hacc, D, wmma::mem_row_major);
    }
}

__device__ __forceinline__ void fma_row(float acc[8], uint4 r, float w) {
    __half2* h = (__half2*)&r;
    #pragma unroll
    for (int j = 0; j < 4; j++) {
        float2 f = __half22float2(h[j]);
        acc[2 * j]     += w * f.x;
        acc[2 * j + 1] += w * f.y;
    }
}

// out[v] = b + (1/deg) * sum_e ew_e * y[src_e]; 16 lanes per node (2 nodes/warp).
// Phase 1: stage the node's edge list into smem. Phase 2: row gathers with
// addresses from LDS (breaks the edge->row dependent L2 chain). Re-arms g_cnt.
__global__ void __launch_bounds__(256)
k_gather(const float* __restrict__ b, float* __restrict__ out) {
    __shared__ float2 se[16][CAP];   // 12288 B
    int t = blockIdx.x * blockDim.x + threadIdx.x;
    int v = t >> 4;
    int grp = (threadIdx.x >> 4);
    int lane = t & 15;
    if (v >= N_NODES) return;
    int cnt = g_cnt[v];
    if (lane == 0) g_cnt[v] = 0;
    if (cnt > CAP) cnt = CAP;
    const float2* ep = g_edge + (size_t)v * CAP;

    for (int i = lane; i < cnt; i += 16) se[grp][i] = ep[i];
    __syncwarp();

    const uint4* y4 = (const uint4*)g_y;   // one row = 16 uint4 (256 B)
    const float2* sep = se[grp];

    float acc[8] = {};
    int i = 0;
    for (; i + 4 <= cnt; i += 4) {
        float2 e0 = sep[i],     e1 = sep[i + 1];
        float2 e2 = sep[i + 2], e3 = sep[i + 3];
        uint4 r0 = y4[(size_t)__float_as_int(e0.x) * 16 + lane];
        uint4 r1 = y4[(size_t)__float_as_int(e1.x) * 16 + lane];
        uint4 r2 = y4[(size_t)__float_as_int(e2.x) * 16 + lane];
        uint4 r3 = y4[(size_t)__float_as_int(e3.x) * 16 + lane];
        fma_row(acc, r0, e0.y);
        fma_row(acc, r1, e1.y);
        fma_row(acc, r2, e2.y);
        fma_row(acc, r3, e3.y);
    }
    for (; i < cnt; i++) {
        float2 ee = sep[i];
        uint4 r = y4[(size_t)__float_as_int(ee.x) * 16 + lane];
        fma_row(acc, r, ee.y);
    }
    float inv = (cnt > 0) ? 1.0f / (float)cnt : 0.0f;
    float4 b0 = ((const float4*)b)[lane * 2];
    float4 b1 = ((const float4*)b)[lane * 2 + 1];
    float4 o0 = make_float4(b0.x + inv * acc[0], b0.y + inv * acc[1],
                            b0.z + inv * acc[2], b0.w + inv * acc[3]);
    float4 o1 = make_float4(b1.x + inv * acc[4], b1.y + inv * acc[5],
                            b1.z + inv * acc[6], b1.w + inv * acc[7]);
    float4* orow = ((float4*)out) + (size_t)v * 32;
    orow[lane * 2]     = o0;
    orow[lane * 2 + 1] = o1;
}

// g_y must be padded: gemm writes full 128-row tiles (313*128 = 40064 rows)
__device__ __half g_y_pad[(313 * 128 - N_NODES) * D];  // keeps tile stores in-bounds

// ---------------------------------------------------------------
extern "C" void kernel_launch(void* const* d_in, const int* in_sizes, int n_in,
                              void* d_out, int out_size) {
    const float* x   = (const float*)d_in[0];
    const int*   src = (const int*)  d_in[1];
    const int*   dst = (const int*)  d_in[2];
    const float* ew  = (const float*)d_in[3];
    const float* W   = (const float*)d_in[4];
    const float* b   = (const float*)d_in[5];
    float* out = (float*)d_out;

    // side stream + events for fork/join inside graph capture
    cudaStream_t s1;
    cudaStreamCreateWithFlags(&s1, cudaStreamNonBlocking);
    cudaEvent_t e_fork, e_join;
    cudaEventCreateWithFlags(&e_fork, cudaEventDisableTiming);
    cudaEventCreateWithFlags(&e_join, cudaEventDisableTiming);

    // fork: tensor-core GEMM branch (independent of edge bucketing)
    cudaEventRecord(e_fork, 0);
    cudaStreamWaitEvent(s1, e_fork, 0);
    k_wh<<<16, 256, 0, s1>>>(W);
    const int gemm_smem = (128 + 128) * XH_LD * (int)sizeof(__half);  // 69632? no:
    // xh = 128*XH_LD halves (34816 B) + wh = 128*XH_LD halves (34816 B) would be 69632;
    // but wh only needs 128 rows x XH_LD halves for fp16 W -> same 34816. Use layout:
    // [xh 128*XH_LD][wh 128*XH_LD] but wh loaded from fp16 source. Shrink: wh needs
    // 128*XH_LD*2 = 34816 B. Total = 69632 B. To hit 52.2KB, use XH_LD for xh and
    // pack wh tight (stride 136 halves kept for conflict avoidance).
    // NOTE: actual allocation below is xh + wh = 2 * 128 * XH_LD * 2 bytes.
    cudaFuncSetAttribute(k_gemm, cudaFuncAttributeMaxDynamicSharedMemorySize,
                         2 * 128 * XH_LD * (int)sizeof(__half));
    k_gemm<<<(N_NODES + 127) / 128, 256, 2 * 128 * XH_LD * (int)sizeof(__half), s1>>>(x);
    cudaEventRecord(e_join, s1);
    (void)gemm_smem;

    // main branch: single-pass bucketed edge fill
    // (g_cnt zeroed by previous call's k_gather; zero-init at module load first time)
    k_fill<<<(N_EDGES / 4 + 255) / 256, 256>>>((const int4*)src, (const int4*)dst,
                                               (const float4*)ew);

    // join, then gather (needs both y and buckets)
    cudaStreamWaitEvent(0, e_join, 0);
    k_gather<<<(N_NODES * 16 + 255) / 256, 256>>>(b, out);
}